// round 1
// baseline (speedup 1.0000x reference)
#include <cuda_runtime.h>
#include <cstdint>

// Problem constants (from reference)
#define NU 100000
#define NI 50000
#define NN 150000           // NU + NI
#define DIM 64
#define NE 3000000
#define DELTA 0.5f

// Scratch: two ping-pong node-feature buffers (38.4 MB each). __device__ globals
// are the allowed scratch mechanism (no cudaMalloc permitted).
__device__ float g_bufA[(size_t)NN * DIM];
__device__ float g_bufB[(size_t)NN * DIM];

// ---------------------------------------------------------------------------
// Build ego = concat(pref[NU,64], repre[NI,64]) into out.
// One float4 per thread.
// ---------------------------------------------------------------------------
__global__ void build_ego_kernel(const float4* __restrict__ pref,
                                 const float4* __restrict__ repre,
                                 float4* __restrict__ out) {
    int i = blockIdx.x * blockDim.x + threadIdx.x;
    const int total = NN * DIM / 4;
    const int userEnd = NU * DIM / 4;
    if (i >= total) return;
    out[i] = (i < userEnd) ? pref[i] : repre[i - userEnd];
}

// ---------------------------------------------------------------------------
// out = DELTA * in  (initializes the accumulation target for the scatter pass,
// fusing the residual "side + DELTA*ego" into the segment-sum base).
// ---------------------------------------------------------------------------
__global__ void scale_init_kernel(const float4* __restrict__ in,
                                  float4* __restrict__ out) {
    int i = blockIdx.x * blockDim.x + threadIdx.x;
    const int total = NN * DIM / 4;
    if (i >= total) return;
    float4 v = in[i];
    v.x *= DELTA; v.y *= DELTA; v.z *= DELTA; v.w *= DELTA;
    out[i] = v;
}

// ---------------------------------------------------------------------------
// Scatter pass: for each edge e, out[dst[e]] += x[src[e]] * w[e].
// 16 threads per edge, one float4 per thread. Scatter via red.global.add.v4.f32
// (sm_90+): 16B vector reduction, no return -> REDG, 4x fewer L2 atomic ops
// than scalar atomicAdd.
// ---------------------------------------------------------------------------
__global__ void __launch_bounds__(256)
scatter_kernel(const int* __restrict__ src,
               const int* __restrict__ dst,
               const float* __restrict__ w,
               const float* __restrict__ x,
               float* __restrict__ out) {
    long long t = (long long)blockIdx.x * blockDim.x + threadIdx.x;
    int e = (int)(t >> 4);
    int j = (int)(t & 15);
    if (e >= NE) return;

    int s  = __ldg(src + e);
    int d  = __ldg(dst + e);
    float wt = __ldg(w + e);

    const float4* xp = reinterpret_cast<const float4*>(x) + (size_t)s * 16 + j;
    float4 v = __ldg(xp);
    v.x *= wt; v.y *= wt; v.z *= wt; v.w *= wt;

    float* op = out + (size_t)d * DIM + (size_t)j * 4;
    asm volatile("red.global.add.v4.f32 [%0], {%1, %2, %3, %4};"
                 :: "l"(op), "f"(v.x), "f"(v.y), "f"(v.z), "f"(v.w)
                 : "memory");
}

// ---------------------------------------------------------------------------
// Write a finished modality into d_out with the concat layout:
//   user_preference[NU,128] = [user_img | user_txt]   at rows 0..NU
//   items[NI,128]           = [item_img | item_txt]   following it
// d_out flat layout assumed: user_preference.ravel() then items.ravel().
// halfOff = 0 for img modality, 64 for txt modality.
// ---------------------------------------------------------------------------
__global__ void write_out_kernel(const float4* __restrict__ ego,
                                 float* __restrict__ out,
                                 int halfOff) {
    long long t = (long long)blockIdx.x * blockDim.x + threadIdx.x;
    int node = (int)(t >> 4);
    int j = (int)(t & 15);
    if (node >= NN) return;
    float4 v = ego[(size_t)node * 16 + j];
    size_t base;
    if (node < NU) {
        base = (size_t)node * 128 + halfOff;
    } else {
        base = (size_t)NU * 128 + (size_t)(node - NU) * 128 + halfOff;
    }
    *reinterpret_cast<float4*>(out + base + (size_t)j * 4) = v;
}

// ---------------------------------------------------------------------------
// Launch orchestration
// ---------------------------------------------------------------------------
static void run_modality(const int* edge_index,      // (2, NE): first NE = src, next NE = dst
                         const float* edge_weight,   // (NE, 1)
                         const float* preference,    // (NU, 64)
                         const float* repre,         // (NI, 64)
                         float* d_out,
                         int halfOff,
                         float* bufA, float* bufB,
                         cudaStream_t s) {
    const int* src = edge_index;
    const int* dst = edge_index + NE;

    const int elemThreads = 256;
    const int elemBlocks  = (NN * DIM / 4 + elemThreads - 1) / elemThreads;

    const long long scatterThreads = (long long)NE * 16;
    const int sThreads = 256;
    const int sBlocks  = (int)((scatterThreads + sThreads - 1) / sThreads);

    // ego -> bufA
    build_ego_kernel<<<elemBlocks, elemThreads, 0, s>>>(
        reinterpret_cast<const float4*>(preference),
        reinterpret_cast<const float4*>(repre),
        reinterpret_cast<float4*>(bufA));

    // Layer 1: bufB = 0.5*bufA + scatter(bufA)
    scale_init_kernel<<<elemBlocks, elemThreads, 0, s>>>(
        reinterpret_cast<const float4*>(bufA), reinterpret_cast<float4*>(bufB));
    scatter_kernel<<<sBlocks, sThreads, 0, s>>>(src, dst, edge_weight, bufA, bufB);

    // Layer 2: bufA = 0.5*bufB + scatter(bufB)
    scale_init_kernel<<<elemBlocks, elemThreads, 0, s>>>(
        reinterpret_cast<const float4*>(bufB), reinterpret_cast<float4*>(bufA));
    scatter_kernel<<<sBlocks, sThreads, 0, s>>>(src, dst, edge_weight, bufB, bufA);

    // Layer 3: bufB = 0.5*bufA + scatter(bufA)
    scale_init_kernel<<<elemBlocks, elemThreads, 0, s>>>(
        reinterpret_cast<const float4*>(bufA), reinterpret_cast<float4*>(bufB));
    scatter_kernel<<<sBlocks, sThreads, 0, s>>>(src, dst, edge_weight, bufA, bufB);

    // Emit into d_out at the right column half
    const long long outThreads = (long long)NN * 16;
    const int oBlocks = (int)((outThreads + 255) / 256);
    write_out_kernel<<<oBlocks, 256, 0, s>>>(
        reinterpret_cast<const float4*>(bufB), d_out, halfOff);
}

extern "C" void kernel_launch(void* const* d_in, const int* in_sizes, int n_in,
                              void* d_out, int out_size) {
    // Input order (metadata):
    // 0: edge_index_img  (2, E)  int32
    // 1: edge_weight_img (E, 1)  float32
    // 2: edge_index_txt  (2, E)  int32
    // 3: edge_weight_txt (E, 1)  float32
    // 4: image_preference (NU, 64) float32
    // 5: text_preference  (NU, 64) float32
    // 6: image_repre      (NI, 64) float32
    // 7: text_repre       (NI, 64) float32
    const int*   ei_img = (const int*)  d_in[0];
    const float* ew_img = (const float*)d_in[1];
    const int*   ei_txt = (const int*)  d_in[2];
    const float* ew_txt = (const float*)d_in[3];
    const float* img_pref = (const float*)d_in[4];
    const float* txt_pref = (const float*)d_in[5];
    const float* img_repr = (const float*)d_in[6];
    const float* txt_repr = (const float*)d_in[7];
    float* out = (float*)d_out;

    float* bufA; float* bufB;
    cudaGetSymbolAddress((void**)&bufA, g_bufA);
    cudaGetSymbolAddress((void**)&bufB, g_bufB);

    cudaStream_t s = 0;  // capture stream (harness passes work via legacy default or captures this)
    // NOTE: we launch on the default stream; the harness captures these launches.

    run_modality(ei_img, ew_img, img_pref, img_repr, out, /*halfOff=*/0,  bufA, bufB, s);
    run_modality(ei_txt, ew_txt, txt_pref, txt_repr, out, /*halfOff=*/64, bufA, bufB, s);
}

// round 3
// speedup vs baseline: 2.1122x; 2.1122x over previous
#include <cuda_runtime.h>
#include <cstdint>

// Problem constants (from reference)
#define NU 100000
#define NI 50000
#define NN 150000           // NU + NI
#define DIM 64
#define NE 3000000
#define DELTA 0.5f

#define SCAN_CHUNK 1024
#define N_CHUNKS ((NN + SCAN_CHUNK - 1) / SCAN_CHUNK)   // 147

// ---------------------------------------------------------------------------
// __device__ global scratch (no cudaMalloc allowed).
//   bufA / bufB : ping-pong node feature buffers (38.4 MB each)
//   deg/off/cursor : per-node degree / CSC offsets / scatter cursors
//   sorted_sw   : dst-sorted packed edges {src, w-bits} (24 MB)
// ---------------------------------------------------------------------------
__device__ float  g_bufA[(size_t)NN * DIM];
__device__ float  g_bufB[(size_t)NN * DIM];
__device__ int    g_deg[NN];
__device__ int    g_off[NN];
__device__ int    g_cursor[NN];
__device__ int    g_partials[N_CHUNKS];
__device__ int    g_partials_scanned[N_CHUNKS];
__device__ uint2  g_sorted_sw[NE];

// ---------------------------------------------------------------------------
// Counting sort by dst: step 1 — zero degree counters
// ---------------------------------------------------------------------------
__global__ void zero_deg_kernel(int* __restrict__ deg) {
    int i = blockIdx.x * blockDim.x + threadIdx.x;
    if (i < NN) deg[i] = 0;
}

// step 2 — histogram of dst
__global__ void __launch_bounds__(256)
hist_kernel(const int* __restrict__ dst, int* __restrict__ deg) {
    int e = blockIdx.x * blockDim.x + threadIdx.x;
    if (e >= NE) return;
    atomicAdd(deg + __ldg(dst + e), 1);
}

// step 3a — per-chunk exclusive scan (Hillis-Steele in smem), chunk totals to partials
__global__ void __launch_bounds__(SCAN_CHUNK)
scan1_kernel(const int* __restrict__ deg, int* __restrict__ off,
             int* __restrict__ partials) {
    __shared__ int sm[2][SCAN_CHUNK];
    int t = threadIdx.x;
    int i = blockIdx.x * SCAN_CHUNK + t;
    int v = (i < NN) ? deg[i] : 0;
    sm[0][t] = v;
    __syncthreads();
    int cur = 0;
    #pragma unroll
    for (int ofs = 1; ofs < SCAN_CHUNK; ofs <<= 1) {
        int nxt = cur ^ 1;
        int val = sm[cur][t];
        if (t >= ofs) val += sm[cur][t - ofs];
        sm[nxt][t] = val;
        __syncthreads();
        cur = nxt;
    }
    int inclusive = sm[cur][t];
    if (i < NN) off[i] = inclusive - v;        // exclusive within chunk
    if (t == SCAN_CHUNK - 1) partials[blockIdx.x] = inclusive;
}

// step 3b — scan the 147 chunk totals (single thread; trivial size)
__global__ void scan2_kernel(const int* __restrict__ partials,
                             int* __restrict__ scanned) {
    if (threadIdx.x == 0 && blockIdx.x == 0) {
        int acc = 0;
        for (int b = 0; b < N_CHUNKS; b++) {
            scanned[b] = acc;
            acc += partials[b];
        }
    }
}

// step 3c — add chunk bases; also initialize cursors
__global__ void scan3_kernel(int* __restrict__ off,
                             const int* __restrict__ scanned,
                             int* __restrict__ cursor) {
    int i = blockIdx.x * blockDim.x + threadIdx.x;
    if (i >= NN) return;
    int o = off[i] + scanned[i / SCAN_CHUNK];
    off[i] = o;
    cursor[i] = o;
}

// step 4 — scatter packed (src, w) into dst-sorted position
__global__ void __launch_bounds__(256)
sort_scatter_kernel(const int* __restrict__ src, const int* __restrict__ dst,
                    const float* __restrict__ w,
                    int* __restrict__ cursor, uint2* __restrict__ sw) {
    int e = blockIdx.x * blockDim.x + threadIdx.x;
    if (e >= NE) return;
    int d = __ldg(dst + e);
    int pos = atomicAdd(cursor + d, 1);
    sw[pos] = make_uint2((unsigned)__ldg(src + e), __float_as_uint(__ldg(w + e)));
}

// ---------------------------------------------------------------------------
// Pull kernel: out[d] = DELTA * ego[d] + sum_{e: dst=d} w_e * x[src_e]
// 16 lanes per dst node, one float4 lane each. No atomics.
// Edge loop unrolled x2 with prefetch: keeps >=2 independent gather loads
// in flight per lane to cover the ~234cyc L2-hit latency.
//
// SPLIT_IN:  gather (and residual) read directly from pref/repre (layer 1).
// TO_OUT:    write into d_out with the concat layout at column halfOff (layer 3).
// ---------------------------------------------------------------------------
template<bool SPLIT_IN, bool TO_OUT>
__global__ void __launch_bounds__(256)
pull_kernel(const uint2* __restrict__ sw,
            const int* __restrict__ off, const int* __restrict__ deg,
            const float4* __restrict__ xA,     // unified input (or pref when SPLIT_IN)
            const float4* __restrict__ xB,     // repre when SPLIT_IN, else unused
            float* __restrict__ out,           // unified buffer or d_out
            int halfOff) {
    int t = blockIdx.x * blockDim.x + threadIdx.x;
    int node = t >> 4;
    int j = t & 15;
    if (node >= NN) return;

    // residual term
    float4 acc;
    if (SPLIT_IN) {
        acc = (node < NU) ? __ldg(xA + (size_t)node * 16 + j)
                          : __ldg(xB + (size_t)(node - NU) * 16 + j);
    } else {
        acc = __ldg(xA + (size_t)node * 16 + j);
    }
    acc.x *= DELTA; acc.y *= DELTA; acc.z *= DELTA; acc.w *= DELTA;
    float4 acc2 = make_float4(0.f, 0.f, 0.f, 0.f);

    const int o = __ldg(off + node);
    const int n = __ldg(deg + node);
    const int end = o + n;

    auto gather = [&](int s) -> float4 {
        if (SPLIT_IN) {
            return (s < NU) ? __ldg(xA + (size_t)s * 16 + j)
                            : __ldg(xB + (size_t)(s - NU) * 16 + j);
        } else {
            return __ldg(xA + (size_t)s * 16 + j);
        }
    };

    int k = o;
    // unroll-by-2: two independent gathers in flight
    for (; k + 1 < end; k += 2) {
        uint2 e0 = __ldg(sw + k);
        uint2 e1 = __ldg(sw + k + 1);
        float4 v0 = gather((int)e0.x);
        float4 v1 = gather((int)e1.x);
        float w0 = __uint_as_float(e0.y);
        float w1 = __uint_as_float(e1.y);
        acc.x  = fmaf(w0, v0.x, acc.x);
        acc.y  = fmaf(w0, v0.y, acc.y);
        acc.z  = fmaf(w0, v0.z, acc.z);
        acc.w  = fmaf(w0, v0.w, acc.w);
        acc2.x = fmaf(w1, v1.x, acc2.x);
        acc2.y = fmaf(w1, v1.y, acc2.y);
        acc2.z = fmaf(w1, v1.z, acc2.z);
        acc2.w = fmaf(w1, v1.w, acc2.w);
    }
    if (k < end) {
        uint2 e0 = __ldg(sw + k);
        float4 v0 = gather((int)e0.x);
        float w0 = __uint_as_float(e0.y);
        acc.x = fmaf(w0, v0.x, acc.x);
        acc.y = fmaf(w0, v0.y, acc.y);
        acc.z = fmaf(w0, v0.z, acc.z);
        acc.w = fmaf(w0, v0.w, acc.w);
    }
    acc.x += acc2.x; acc.y += acc2.y; acc.z += acc2.z; acc.w += acc2.w;

    if (TO_OUT) {
        size_t base = (node < NU)
            ? (size_t)node * 128 + halfOff
            : (size_t)NU * 128 + (size_t)(node - NU) * 128 + halfOff;
        *reinterpret_cast<float4*>(out + base + (size_t)j * 4) = acc;
    } else {
        reinterpret_cast<float4*>(out)[(size_t)node * 16 + j] = acc;
    }
}

// ---------------------------------------------------------------------------
// Orchestration
// ---------------------------------------------------------------------------
struct Scratch {
    float* bufA; float* bufB;
    int *deg, *off, *cursor, *partials, *partials_scanned;
    uint2* sw;
};

static void run_modality(const int* edge_index, const float* edge_weight,
                         const float* preference, const float* repre,
                         float* d_out, int halfOff, const Scratch& sc) {
    const int* src = edge_index;
    const int* dst = edge_index + NE;

    const int nodeBlocks = (NN + 255) / 256;
    const int edgeBlocks = (NE + 255) / 256;
    const int pullBlocks = (NN * 16 + 255) / 256;

    // Build CSC (dst-sorted edge list)
    zero_deg_kernel<<<nodeBlocks, 256>>>(sc.deg);
    hist_kernel<<<edgeBlocks, 256>>>(dst, sc.deg);
    scan1_kernel<<<N_CHUNKS, SCAN_CHUNK>>>(sc.deg, sc.off, sc.partials);
    scan2_kernel<<<1, 32>>>(sc.partials, sc.partials_scanned);
    scan3_kernel<<<nodeBlocks, 256>>>(sc.off, sc.partials_scanned, sc.cursor);
    sort_scatter_kernel<<<edgeBlocks, 256>>>(src, dst, edge_weight, sc.cursor, sc.sw);

    // Layer 1: read pref/repre directly -> bufB
    pull_kernel<true, false><<<pullBlocks, 256>>>(
        sc.sw, sc.off, sc.deg,
        reinterpret_cast<const float4*>(preference),
        reinterpret_cast<const float4*>(repre),
        sc.bufB, 0);
    // Layer 2: bufB -> bufA
    pull_kernel<false, false><<<pullBlocks, 256>>>(
        sc.sw, sc.off, sc.deg,
        reinterpret_cast<const float4*>(sc.bufB), nullptr,
        sc.bufA, 0);
    // Layer 3: bufA -> d_out (concat layout)
    pull_kernel<false, true><<<pullBlocks, 256>>>(
        sc.sw, sc.off, sc.deg,
        reinterpret_cast<const float4*>(sc.bufA), nullptr,
        d_out, halfOff);
}

extern "C" void kernel_launch(void* const* d_in, const int* in_sizes, int n_in,
                              void* d_out, int out_size) {
    const int*   ei_img   = (const int*)  d_in[0];
    const float* ew_img   = (const float*)d_in[1];
    const int*   ei_txt   = (const int*)  d_in[2];
    const float* ew_txt   = (const float*)d_in[3];
    const float* img_pref = (const float*)d_in[4];
    const float* txt_pref = (const float*)d_in[5];
    const float* img_repr = (const float*)d_in[6];
    const float* txt_repr = (const float*)d_in[7];
    float* out = (float*)d_out;

    Scratch sc;
    cudaGetSymbolAddress((void**)&sc.bufA, g_bufA);
    cudaGetSymbolAddress((void**)&sc.bufB, g_bufB);
    cudaGetSymbolAddress((void**)&sc.deg, g_deg);
    cudaGetSymbolAddress((void**)&sc.off, g_off);
    cudaGetSymbolAddress((void**)&sc.cursor, g_cursor);
    cudaGetSymbolAddress((void**)&sc.partials, g_partials);
    cudaGetSymbolAddress((void**)&sc.partials_scanned, g_partials_scanned);
    cudaGetSymbolAddress((void**)&sc.sw, g_sorted_sw);

    run_modality(ei_img, ew_img, img_pref, img_repr, out, /*halfOff=*/0,  sc);
    run_modality(ei_txt, ew_txt, txt_pref, txt_repr, out, /*halfOff=*/64, sc);
}

// round 4
// speedup vs baseline: 2.1355x; 1.0110x over previous
#include <cuda_runtime.h>
#include <cstdint>

// Problem constants (from reference)
#define NU 100000
#define NI 50000
#define NN 150000           // NU + NI
#define DIM 64
#define NE 3000000
#define DELTA 0.5f

#define SCAN_CHUNK 1024
#define N_CHUNKS ((NN + SCAN_CHUNK - 1) / SCAN_CHUNK)   // 147

#define EDGE_BLOCKS ((NE + 255) / 256)                  // 11719
#define PULL_BLOCKS ((NN * 16 + 255) / 256)             // 9375
#define NODE2_BLOCKS ((2 * NN + 255) / 256)

// ---------------------------------------------------------------------------
// __device__ global scratch (no cudaMalloc allowed). Both modalities packed:
// modality m uses deg/off/cursor[m*NN..], sw[m], buf*[m].
// ---------------------------------------------------------------------------
__device__ float  g_buf1[2][(size_t)NN * DIM];   // layer-1 outputs
__device__ float  g_buf2[2][(size_t)NN * DIM];   // layer-2 outputs
__device__ int    g_deg[2 * NN];
__device__ int    g_off[2 * NN];
__device__ int    g_cursor[2 * NN];
__device__ int    g_partials[2 * N_CHUNKS];
__device__ int    g_scanned[2 * N_CHUNKS];
__device__ uint2  g_sw[2][(size_t)NE];

// ---------------------------------------------------------------------------
// step 1 — zero both degree arrays
// ---------------------------------------------------------------------------
__global__ void zero_deg_kernel(int* __restrict__ deg) {
    int i = blockIdx.x * blockDim.x + threadIdx.x;
    if (i < 2 * NN) deg[i] = 0;
}

// step 2 — fused histogram of both modalities' dst
__global__ void __launch_bounds__(256)
hist_kernel(const int* __restrict__ dst0, const int* __restrict__ dst1,
            int* __restrict__ deg) {
    int b = blockIdx.x;
    int m = (b >= EDGE_BLOCKS) ? 1 : 0;
    int e = (b - m * EDGE_BLOCKS) * 256 + threadIdx.x;
    if (e >= NE) return;
    const int* dst = m ? dst1 : dst0;
    atomicAdd(deg + m * NN + __ldg(dst + e), 1);
}

// step 3a — per-chunk exclusive scan, fused over both modalities
__global__ void __launch_bounds__(SCAN_CHUNK)
scan1_kernel(const int* __restrict__ deg, int* __restrict__ off,
             int* __restrict__ partials) {
    __shared__ int sm[2][SCAN_CHUNK];
    int b = blockIdx.x;
    int m = (b >= N_CHUNKS) ? 1 : 0;
    int chunk = b - m * N_CHUNKS;
    int t = threadIdx.x;
    int li = chunk * SCAN_CHUNK + t;                    // local node index
    int v = (li < NN) ? deg[m * NN + li] : 0;
    sm[0][t] = v;
    __syncthreads();
    int cur = 0;
    #pragma unroll
    for (int ofs = 1; ofs < SCAN_CHUNK; ofs <<= 1) {
        int nxt = cur ^ 1;
        int val = sm[cur][t];
        if (t >= ofs) val += sm[cur][t - ofs];
        sm[nxt][t] = val;
        __syncthreads();
        cur = nxt;
    }
    int inclusive = sm[cur][t];
    if (li < NN) off[m * NN + li] = inclusive - v;      // exclusive within chunk
    if (t == SCAN_CHUNK - 1) partials[m * N_CHUNKS + chunk] = inclusive;
}

// step 3b — parallel scan of chunk totals; grid=2 (one block per modality)
__global__ void __launch_bounds__(256)
scan2_kernel(const int* __restrict__ partials, int* __restrict__ scanned) {
    __shared__ int sm[2][256];
    int m = blockIdx.x;
    int t = threadIdx.x;
    int v = (t < N_CHUNKS) ? partials[m * N_CHUNKS + t] : 0;
    sm[0][t] = v;
    __syncthreads();
    int cur = 0;
    #pragma unroll
    for (int ofs = 1; ofs < 256; ofs <<= 1) {
        int nxt = cur ^ 1;
        int val = sm[cur][t];
        if (t >= ofs) val += sm[cur][t - ofs];
        sm[nxt][t] = val;
        __syncthreads();
        cur = nxt;
    }
    if (t < N_CHUNKS) scanned[m * N_CHUNKS + t] = sm[cur][t] - v;  // exclusive
}

// step 3c — add chunk bases; init cursors (fused over both modalities)
__global__ void scan3_kernel(int* __restrict__ off,
                             const int* __restrict__ scanned,
                             int* __restrict__ cursor) {
    int i = blockIdx.x * blockDim.x + threadIdx.x;
    if (i >= 2 * NN) return;
    int m = (i >= NN) ? 1 : 0;
    int li = i - m * NN;
    int o = off[i] + scanned[m * N_CHUNKS + li / SCAN_CHUNK];
    off[i] = o;
    cursor[i] = o;
}

// step 4 — fused scatter of packed (src, w) into dst-sorted position
__global__ void __launch_bounds__(256)
sort_scatter_kernel(const int* __restrict__ src0, const int* __restrict__ dst0,
                    const float* __restrict__ w0,
                    const int* __restrict__ src1, const int* __restrict__ dst1,
                    const float* __restrict__ w1,
                    int* __restrict__ cursor, uint2* __restrict__ sw) {
    int b = blockIdx.x;
    int m = (b >= EDGE_BLOCKS) ? 1 : 0;
    int e = (b - m * EDGE_BLOCKS) * 256 + threadIdx.x;
    if (e >= NE) return;
    const int* src = m ? src1 : src0;
    const int* dst = m ? dst1 : dst0;
    const float* w = m ? w1 : w0;
    int d = __ldg(dst + e);
    int pos = atomicAdd(cursor + m * NN + d, 1);
    sw[(size_t)m * NE + pos] =
        make_uint2((unsigned)__ldg(src + e), __float_as_uint(__ldg(w + e)));
}

// ---------------------------------------------------------------------------
// Fused pull kernel: for each modality m and dst node d,
//   out[d] = DELTA * ego[d] + sum_{e: dst=d} w_e * x[src_e]
// 16 lanes per node, one float4 lane each. Unroll-2 for gather MLP.
// SPLIT_IN: layer 1 — gather/residual read directly from pref/repre.
// TO_OUT:   layer 3 — write d_out concat layout at column m*64.
// ---------------------------------------------------------------------------
template<bool SPLIT_IN, bool TO_OUT>
__global__ void __launch_bounds__(256)
pull_kernel(const uint2* __restrict__ swBase,
            const int* __restrict__ offBase, const int* __restrict__ degBase,
            const float4* __restrict__ xA0, const float4* __restrict__ xB0,
            const float4* __restrict__ xA1, const float4* __restrict__ xB1,
            float* __restrict__ out0, float* __restrict__ out1) {
    int b = blockIdx.x;
    int m = (b >= PULL_BLOCKS) ? 1 : 0;
    int t = (b - m * PULL_BLOCKS) * 256 + threadIdx.x;
    int node = t >> 4;
    int j = t & 15;
    if (node >= NN) return;

    const uint2* sw = swBase + (size_t)m * NE;
    const int* off = offBase + m * NN;
    const int* deg = degBase + m * NN;
    const float4* xA = m ? xA1 : xA0;
    const float4* xB = m ? xB1 : xB0;

    // residual term
    float4 acc;
    if (SPLIT_IN) {
        acc = (node < NU) ? __ldg(xA + (size_t)node * 16 + j)
                          : __ldg(xB + (size_t)(node - NU) * 16 + j);
    } else {
        acc = __ldg(xA + (size_t)node * 16 + j);
    }
    acc.x *= DELTA; acc.y *= DELTA; acc.z *= DELTA; acc.w *= DELTA;
    float4 acc2 = make_float4(0.f, 0.f, 0.f, 0.f);

    const int o = __ldg(off + node);
    const int n = __ldg(deg + node);
    const int end = o + n;

    auto gather = [&](int s) -> float4 {
        if (SPLIT_IN) {
            return (s < NU) ? __ldg(xA + (size_t)s * 16 + j)
                            : __ldg(xB + (size_t)(s - NU) * 16 + j);
        } else {
            return __ldg(xA + (size_t)s * 16 + j);
        }
    };

    int k = o;
    for (; k + 1 < end; k += 2) {       // two independent gathers in flight
        uint2 e0 = __ldg(sw + k);
        uint2 e1 = __ldg(sw + k + 1);
        float4 v0 = gather((int)e0.x);
        float4 v1 = gather((int)e1.x);
        float w0 = __uint_as_float(e0.y);
        float w1 = __uint_as_float(e1.y);
        acc.x  = fmaf(w0, v0.x, acc.x);
        acc.y  = fmaf(w0, v0.y, acc.y);
        acc.z  = fmaf(w0, v0.z, acc.z);
        acc.w  = fmaf(w0, v0.w, acc.w);
        acc2.x = fmaf(w1, v1.x, acc2.x);
        acc2.y = fmaf(w1, v1.y, acc2.y);
        acc2.z = fmaf(w1, v1.z, acc2.z);
        acc2.w = fmaf(w1, v1.w, acc2.w);
    }
    if (k < end) {
        uint2 e0 = __ldg(sw + k);
        float4 v0 = gather((int)e0.x);
        float w0 = __uint_as_float(e0.y);
        acc.x = fmaf(w0, v0.x, acc.x);
        acc.y = fmaf(w0, v0.y, acc.y);
        acc.z = fmaf(w0, v0.z, acc.z);
        acc.w = fmaf(w0, v0.w, acc.w);
    }
    acc.x += acc2.x; acc.y += acc2.y; acc.z += acc2.z; acc.w += acc2.w;

    if (TO_OUT) {
        // out0 == out1 == d_out; column half = m*64
        int halfOff = m * 64;
        size_t base = (node < NU)
            ? (size_t)node * 128 + halfOff
            : (size_t)NU * 128 + (size_t)(node - NU) * 128 + halfOff;
        *reinterpret_cast<float4*>(out0 + base + (size_t)j * 4) = acc;
    } else {
        float* out = m ? out1 : out0;
        reinterpret_cast<float4*>(out)[(size_t)node * 16 + j] = acc;
    }
}

// ---------------------------------------------------------------------------
// Orchestration: 9 launches total.
// ---------------------------------------------------------------------------
extern "C" void kernel_launch(void* const* d_in, const int* in_sizes, int n_in,
                              void* d_out, int out_size) {
    const int*   ei_img   = (const int*)  d_in[0];
    const float* ew_img   = (const float*)d_in[1];
    const int*   ei_txt   = (const int*)  d_in[2];
    const float* ew_txt   = (const float*)d_in[3];
    const float* img_pref = (const float*)d_in[4];
    const float* txt_pref = (const float*)d_in[5];
    const float* img_repr = (const float*)d_in[6];
    const float* txt_repr = (const float*)d_in[7];
    float* out = (float*)d_out;

    const int* src0 = ei_img;        const int* dst0 = ei_img + NE;
    const int* src1 = ei_txt;        const int* dst1 = ei_txt + NE;

    float *buf1_0, *buf1_1, *buf2_0, *buf2_1;
    int *deg, *off, *cursor, *partials, *scanned;
    uint2* sw;
    cudaGetSymbolAddress((void**)&buf1_0, g_buf1);
    cudaGetSymbolAddress((void**)&buf2_0, g_buf2);
    cudaGetSymbolAddress((void**)&deg, g_deg);
    cudaGetSymbolAddress((void**)&off, g_off);
    cudaGetSymbolAddress((void**)&cursor, g_cursor);
    cudaGetSymbolAddress((void**)&partials, g_partials);
    cudaGetSymbolAddress((void**)&scanned, g_scanned);
    cudaGetSymbolAddress((void**)&sw, g_sw);
    buf1_1 = buf1_0 + (size_t)NN * DIM;
    buf2_1 = buf2_0 + (size_t)NN * DIM;

    // Build both CSCs (fused)
    zero_deg_kernel<<<NODE2_BLOCKS, 256>>>(deg);
    hist_kernel<<<2 * EDGE_BLOCKS, 256>>>(dst0, dst1, deg);
    scan1_kernel<<<2 * N_CHUNKS, SCAN_CHUNK>>>(deg, off, partials);
    scan2_kernel<<<2, 256>>>(partials, scanned);
    scan3_kernel<<<NODE2_BLOCKS, 256>>>(off, scanned, cursor);
    sort_scatter_kernel<<<2 * EDGE_BLOCKS, 256>>>(
        src0, dst0, ew_img, src1, dst1, ew_txt, cursor, sw);

    // Layer 1: pref/repre -> buf1 (both modalities)
    pull_kernel<true, false><<<2 * PULL_BLOCKS, 256>>>(
        sw, off, deg,
        reinterpret_cast<const float4*>(img_pref),
        reinterpret_cast<const float4*>(img_repr),
        reinterpret_cast<const float4*>(txt_pref),
        reinterpret_cast<const float4*>(txt_repr),
        buf1_0, buf1_1);
    // Layer 2: buf1 -> buf2
    pull_kernel<false, false><<<2 * PULL_BLOCKS, 256>>>(
        sw, off, deg,
        reinterpret_cast<const float4*>(buf1_0), nullptr,
        reinterpret_cast<const float4*>(buf1_1), nullptr,
        buf2_0, buf2_1);
    // Layer 3: buf2 -> d_out (concat layout)
    pull_kernel<false, true><<<2 * PULL_BLOCKS, 256>>>(
        sw, off, deg,
        reinterpret_cast<const float4*>(buf2_0), nullptr,
        reinterpret_cast<const float4*>(buf2_1), nullptr,
        out, out);
}

// round 5
// speedup vs baseline: 2.2298x; 1.0442x over previous
#include <cuda_runtime.h>
#include <cuda_fp16.h>
#include <cstdint>

// Problem constants (from reference)
#define NU 100000
#define NI 50000
#define NN 150000           // NU + NI
#define DIM 64
#define NE 3000000
#define DELTA 0.5f

#define SCAN_CHUNK 1024
#define N_CHUNKS ((NN + SCAN_CHUNK - 1) / SCAN_CHUNK)   // 147

#define EDGE_BLOCKS ((NE + 255) / 256)                  // 11719
#define PULL_BLOCKS ((NN * 16 + 255) / 256)             // 9375
#define NODE2_BLOCKS ((2 * NN + 255) / 256)

// ---------------------------------------------------------------------------
// __device__ global scratch. Modality m uses slot [m].
//   g_h1 / g_h2 : fp16 node features after layer 1 / layer 2 (19.2 MB each)
//   g_rank      : per-edge within-bucket rank captured during histogram
//   g_sw        : dst-sorted packed edges {src, w-bits}
// ---------------------------------------------------------------------------
__device__ __half g_h1[2][(size_t)NN * DIM];
__device__ __half g_h2[2][(size_t)NN * DIM];
__device__ int    g_deg[2 * NN];
__device__ int    g_off[2 * NN];
__device__ int    g_rank[2 * NE];
__device__ int    g_partials[2 * N_CHUNKS];
__device__ int    g_scanned[2 * N_CHUNKS];
__device__ uint2  g_sw[2][(size_t)NE];

// ---------------------------------------------------------------------------
// step 1 — zero both degree arrays
// ---------------------------------------------------------------------------
__global__ void zero_deg_kernel(int* __restrict__ deg) {
    int i = blockIdx.x * blockDim.x + threadIdx.x;
    if (i < 2 * NN) deg[i] = 0;
}

// step 2 — fused histogram of both modalities' dst; atomicAdd return value is
// the edge's rank within its dst bucket (saved for the atomic-free scatter).
__global__ void __launch_bounds__(256)
hist_kernel(const int* __restrict__ dst0, const int* __restrict__ dst1,
            int* __restrict__ deg, int* __restrict__ rank) {
    int b = blockIdx.x;
    int m = (b >= EDGE_BLOCKS) ? 1 : 0;
    int e = (b - m * EDGE_BLOCKS) * 256 + threadIdx.x;
    if (e >= NE) return;
    const int* dst = m ? dst1 : dst0;
    int d = __ldg(dst + e);
    rank[m * NE + e] = atomicAdd(deg + m * NN + d, 1);
}

// step 3a — per-chunk exclusive scan, fused over both modalities
__global__ void __launch_bounds__(SCAN_CHUNK)
scan1_kernel(const int* __restrict__ deg, int* __restrict__ off,
             int* __restrict__ partials) {
    __shared__ int sm[2][SCAN_CHUNK];
    int b = blockIdx.x;
    int m = (b >= N_CHUNKS) ? 1 : 0;
    int chunk = b - m * N_CHUNKS;
    int t = threadIdx.x;
    int li = chunk * SCAN_CHUNK + t;
    int v = (li < NN) ? deg[m * NN + li] : 0;
    sm[0][t] = v;
    __syncthreads();
    int cur = 0;
    #pragma unroll
    for (int ofs = 1; ofs < SCAN_CHUNK; ofs <<= 1) {
        int nxt = cur ^ 1;
        int val = sm[cur][t];
        if (t >= ofs) val += sm[cur][t - ofs];
        sm[nxt][t] = val;
        __syncthreads();
        cur = nxt;
    }
    int inclusive = sm[cur][t];
    if (li < NN) off[m * NN + li] = inclusive - v;
    if (t == SCAN_CHUNK - 1) partials[m * N_CHUNKS + chunk] = inclusive;
}

// step 3b — parallel scan of chunk totals; grid=2
__global__ void __launch_bounds__(256)
scan2_kernel(const int* __restrict__ partials, int* __restrict__ scanned) {
    __shared__ int sm[2][256];
    int m = blockIdx.x;
    int t = threadIdx.x;
    int v = (t < N_CHUNKS) ? partials[m * N_CHUNKS + t] : 0;
    sm[0][t] = v;
    __syncthreads();
    int cur = 0;
    #pragma unroll
    for (int ofs = 1; ofs < 256; ofs <<= 1) {
        int nxt = cur ^ 1;
        int val = sm[cur][t];
        if (t >= ofs) val += sm[cur][t - ofs];
        sm[nxt][t] = val;
        __syncthreads();
        cur = nxt;
    }
    if (t < N_CHUNKS) scanned[m * N_CHUNKS + t] = sm[cur][t] - v;  // exclusive
}

// step 3c — add chunk bases
__global__ void scan3_kernel(int* __restrict__ off,
                             const int* __restrict__ scanned) {
    int i = blockIdx.x * blockDim.x + threadIdx.x;
    if (i >= 2 * NN) return;
    int m = (i >= NN) ? 1 : 0;
    int li = i - m * NN;
    off[i] += scanned[m * N_CHUNKS + li / SCAN_CHUNK];
}

// step 4 — atomic-free scatter: pos = off[dst] + rank
__global__ void __launch_bounds__(256)
sort_scatter_kernel(const int* __restrict__ src0, const int* __restrict__ dst0,
                    const float* __restrict__ w0,
                    const int* __restrict__ src1, const int* __restrict__ dst1,
                    const float* __restrict__ w1,
                    const int* __restrict__ off, const int* __restrict__ rank,
                    uint2* __restrict__ sw) {
    int b = blockIdx.x;
    int m = (b >= EDGE_BLOCKS) ? 1 : 0;
    int e = (b - m * EDGE_BLOCKS) * 256 + threadIdx.x;
    if (e >= NE) return;
    const int* src = m ? src1 : src0;
    const int* dst = m ? dst1 : dst0;
    const float* w = m ? w1 : w0;
    int d = __ldg(dst + e);
    int pos = __ldg(off + m * NN + d) + __ldg(rank + m * NE + e);
    sw[(size_t)m * NE + pos] =
        make_uint2((unsigned)__ldg(src + e), __float_as_uint(__ldg(w + e)));
}

// ---------------------------------------------------------------------------
// Fused pull kernel, fp32 accumulation:
//   out[d] = DELTA * x[d] + sum_{e: dst=d} w_e * x[src_e]
// 16 lanes per node; lane j covers features [4j, 4j+4).
//   IN_F16 = false : layer 1, reads fp32 pref/repre (split at NU)
//   IN_F16 = true  : reads fp16 feature buffer (uint2 = 4 halves per lane)
//   TO_OUT = false : writes fp16 buffer
//   TO_OUT = true  : layer 3, writes fp32 d_out in concat layout (col m*64)
// ---------------------------------------------------------------------------
template<bool IN_F16, bool TO_OUT>
__global__ void __launch_bounds__(256)
pull_kernel(const uint2* __restrict__ swBase,
            const int* __restrict__ offBase, const int* __restrict__ degBase,
            const float4* __restrict__ fA0, const float4* __restrict__ fB0,
            const float4* __restrict__ fA1, const float4* __restrict__ fB1,
            const uint2* __restrict__ hIn0, const uint2* __restrict__ hIn1,
            uint2* __restrict__ hOut0, uint2* __restrict__ hOut1,
            float* __restrict__ fout) {
    int b = blockIdx.x;
    int m = (b >= PULL_BLOCKS) ? 1 : 0;
    int t = (b - m * PULL_BLOCKS) * 256 + threadIdx.x;
    int node = t >> 4;
    int j = t & 15;
    if (node >= NN) return;

    const uint2* sw = swBase + (size_t)m * NE;
    const int* off = offBase + m * NN;
    const int* deg = degBase + m * NN;
    const float4* fA = m ? fA1 : fA0;
    const float4* fB = m ? fB1 : fB0;
    const uint2* hIn = m ? hIn1 : hIn0;

    auto gather = [&](int s) -> float4 {
        if (IN_F16) {
            uint2 v = __ldg(hIn + (size_t)s * 16 + j);
            __half2 a = *reinterpret_cast<__half2*>(&v.x);
            __half2 c = *reinterpret_cast<__half2*>(&v.y);
            float2 fa = __half22float2(a);
            float2 fc = __half22float2(c);
            return make_float4(fa.x, fa.y, fc.x, fc.y);
        } else {
            return (s < NU) ? __ldg(fA + (size_t)s * 16 + j)
                            : __ldg(fB + (size_t)(s - NU) * 16 + j);
        }
    };

    // residual term (same buffer as gathers)
    float4 acc = gather(node);
    acc.x *= DELTA; acc.y *= DELTA; acc.z *= DELTA; acc.w *= DELTA;
    float4 acc2 = make_float4(0.f, 0.f, 0.f, 0.f);

    const int o = __ldg(off + node);
    const int n = __ldg(deg + node);
    const int end = o + n;

    int k = o;
    for (; k + 1 < end; k += 2) {       // two independent gathers in flight
        uint2 e0 = __ldg(sw + k);
        uint2 e1 = __ldg(sw + k + 1);
        float4 v0 = gather((int)e0.x);
        float4 v1 = gather((int)e1.x);
        float w0 = __uint_as_float(e0.y);
        float w1 = __uint_as_float(e1.y);
        acc.x  = fmaf(w0, v0.x, acc.x);
        acc.y  = fmaf(w0, v0.y, acc.y);
        acc.z  = fmaf(w0, v0.z, acc.z);
        acc.w  = fmaf(w0, v0.w, acc.w);
        acc2.x = fmaf(w1, v1.x, acc2.x);
        acc2.y = fmaf(w1, v1.y, acc2.y);
        acc2.z = fmaf(w1, v1.z, acc2.z);
        acc2.w = fmaf(w1, v1.w, acc2.w);
    }
    if (k < end) {
        uint2 e0 = __ldg(sw + k);
        float4 v0 = gather((int)e0.x);
        float w0 = __uint_as_float(e0.y);
        acc.x = fmaf(w0, v0.x, acc.x);
        acc.y = fmaf(w0, v0.y, acc.y);
        acc.z = fmaf(w0, v0.z, acc.z);
        acc.w = fmaf(w0, v0.w, acc.w);
    }
    acc.x += acc2.x; acc.y += acc2.y; acc.z += acc2.z; acc.w += acc2.w;

    if (TO_OUT) {
        int halfOff = m * 64;
        size_t base = (node < NU)
            ? (size_t)node * 128 + halfOff
            : (size_t)NU * 128 + (size_t)(node - NU) * 128 + halfOff;
        *reinterpret_cast<float4*>(fout + base + (size_t)j * 4) = acc;
    } else {
        uint2* hOut = m ? hOut1 : hOut0;
        __half2 ha = __floats2half2_rn(acc.x, acc.y);
        __half2 hb = __floats2half2_rn(acc.z, acc.w);
        uint2 ov;
        ov.x = *reinterpret_cast<unsigned*>(&ha);
        ov.y = *reinterpret_cast<unsigned*>(&hb);
        hOut[(size_t)node * 16 + j] = ov;
    }
}

// ---------------------------------------------------------------------------
// Orchestration: 9 launches total.
// ---------------------------------------------------------------------------
extern "C" void kernel_launch(void* const* d_in, const int* in_sizes, int n_in,
                              void* d_out, int out_size) {
    const int*   ei_img   = (const int*)  d_in[0];
    const float* ew_img   = (const float*)d_in[1];
    const int*   ei_txt   = (const int*)  d_in[2];
    const float* ew_txt   = (const float*)d_in[3];
    const float* img_pref = (const float*)d_in[4];
    const float* txt_pref = (const float*)d_in[5];
    const float* img_repr = (const float*)d_in[6];
    const float* txt_repr = (const float*)d_in[7];
    float* out = (float*)d_out;

    const int* src0 = ei_img;        const int* dst0 = ei_img + NE;
    const int* src1 = ei_txt;        const int* dst1 = ei_txt + NE;

    __half *h1_0, *h2_0;
    int *deg, *off, *rank, *partials, *scanned;
    uint2* sw;
    cudaGetSymbolAddress((void**)&h1_0, g_h1);
    cudaGetSymbolAddress((void**)&h2_0, g_h2);
    cudaGetSymbolAddress((void**)&deg, g_deg);
    cudaGetSymbolAddress((void**)&off, g_off);
    cudaGetSymbolAddress((void**)&rank, g_rank);
    cudaGetSymbolAddress((void**)&partials, g_partials);
    cudaGetSymbolAddress((void**)&scanned, g_scanned);
    cudaGetSymbolAddress((void**)&sw, g_sw);
    uint2* h1u0 = reinterpret_cast<uint2*>(h1_0);
    uint2* h1u1 = reinterpret_cast<uint2*>(h1_0 + (size_t)NN * DIM);
    uint2* h2u0 = reinterpret_cast<uint2*>(h2_0);
    uint2* h2u1 = reinterpret_cast<uint2*>(h2_0 + (size_t)NN * DIM);

    // Build both CSCs
    zero_deg_kernel<<<NODE2_BLOCKS, 256>>>(deg);
    hist_kernel<<<2 * EDGE_BLOCKS, 256>>>(dst0, dst1, deg, rank);
    scan1_kernel<<<2 * N_CHUNKS, SCAN_CHUNK>>>(deg, off, partials);
    scan2_kernel<<<2, 256>>>(partials, scanned);
    scan3_kernel<<<NODE2_BLOCKS, 256>>>(off, scanned);
    sort_scatter_kernel<<<2 * EDGE_BLOCKS, 256>>>(
        src0, dst0, ew_img, src1, dst1, ew_txt, off, rank, sw);

    // Layer 1: fp32 pref/repre -> fp16 buf1
    pull_kernel<false, false><<<2 * PULL_BLOCKS, 256>>>(
        sw, off, deg,
        reinterpret_cast<const float4*>(img_pref),
        reinterpret_cast<const float4*>(img_repr),
        reinterpret_cast<const float4*>(txt_pref),
        reinterpret_cast<const float4*>(txt_repr),
        nullptr, nullptr,
        h1u0, h1u1, nullptr);
    // Layer 2: fp16 buf1 -> fp16 buf2
    pull_kernel<true, false><<<2 * PULL_BLOCKS, 256>>>(
        sw, off, deg,
        nullptr, nullptr, nullptr, nullptr,
        h1u0, h1u1,
        h2u0, h2u1, nullptr);
    // Layer 3: fp16 buf2 -> fp32 d_out (concat layout)
    pull_kernel<true, true><<<2 * PULL_BLOCKS, 256>>>(
        sw, off, deg,
        nullptr, nullptr, nullptr, nullptr,
        h2u0, h2u1,
        nullptr, nullptr, out);
}